// round 5
// baseline (speedup 1.0000x reference)
#include <cuda_runtime.h>
#include <math.h>
#include <stdint.h>

#define NB   1024
#define NS   500
#define RR   128
#define LATC 12
#define FEATC 64
#define HIDC 128
#define CINC 21            // 9 raw inputs + 12 folded latent channels
#define GC   13            // grid channels: 1 sdf + 12 latent

typedef unsigned long long u64;

// ---------------- scratch (static device arrays; no runtime alloc) ----------
__device__ float  g_sdf[NB * NS];
__device__ float4 g_rgbp[NB * NS];    // xyz = rgb (16B aligned)
__device__ float  g_cw[CINC * HIDC];  // combined first-layer weights
__device__ float  g_cb[HIDC];         // combined first-layer bias
__device__ float  g_w2t[3 * HIDC];    // W2 transposed [c][j]
__device__ float  g_b2c[3];

// ---------------- packed f32x2 helpers --------------------------------------
__device__ __forceinline__ u64 ffma2(u64 a, u64 b, u64 c) {
    u64 d;
    asm("fma.rn.f32x2 %0, %1, %2, %3;" : "=l"(d) : "l"(a), "l"(b), "l"(c));
    return d;
}
__device__ __forceinline__ u64 pack2(float lo, float hi) {
    u64 d;
    asm("mov.b64 %0, {%1, %2};" : "=l"(d) : "f"(lo), "f"(hi));
    return d;
}
__device__ __forceinline__ void unpack2(u64 v, float& lo, float& hi) {
    asm("mov.b64 {%0, %1}, %2;" : "=f"(lo), "=f"(hi) : "l"(v));
}

// ---------------- fold: feature layer into W1 (warp-parallel) ---------------
// 13 blocks x 512 threads (16 warps). Blocks 0..11: block l, warp w computes
// j = 8w..8w+7 of W_eff[l][:] via lane-parallel 64-term dot + shfl reduction.
// Block 12: bias fold + row copies + W2 transpose.
__global__ void __launch_bounds__(512)
fold_kernel(const float* __restrict__ Wf, const float* __restrict__ bf,
            const float* __restrict__ W1, const float* __restrict__ b1,
            const float* __restrict__ W2, const float* __restrict__ b2) {
    const unsigned FULL = 0xffffffffu;
    int tid = threadIdx.x;
    int warp = tid >> 5, lane = tid & 31;
    int l = blockIdx.x;

    if (l < LATC) {
        float wf0 = Wf[l * FEATC + lane];
        float wf1 = Wf[l * FEATC + 32 + lane];
#pragma unroll
        for (int jj = 0; jj < 8; jj++) {
            int j = warp * 8 + jj;
            float t = fmaf(wf0, W1[(9 + lane) * HIDC + j],
                           wf1 * W1[(9 + 32 + lane) * HIDC + j]);
#pragma unroll
            for (int o = 16; o > 0; o >>= 1) t += __shfl_xor_sync(FULL, t, o);
            if (lane == 0) g_cw[(9 + l) * HIDC + j] = t;
        }
    } else {
        float bf0 = bf[lane];
        float bf1 = bf[32 + lane];
#pragma unroll
        for (int jj = 0; jj < 8; jj++) {
            int j = warp * 8 + jj;
            float t = fmaf(bf0, W1[(9 + lane) * HIDC + j],
                           bf1 * W1[(9 + 32 + lane) * HIDC + j]);
#pragma unroll
            for (int o = 16; o > 0; o >>= 1) t += __shfl_xor_sync(FULL, t, o);
            if (lane == 0) g_cb[j] = b1[j] + t;
        }
        for (int i = tid; i < 9 * HIDC; i += 512) g_cw[i] = W1[i];
        for (int i = tid; i < 3 * HIDC; i += 512) {
            int c = i / HIDC, jj = i - c * HIDC;
            g_w2t[i] = W2[jj * 3 + c];
        }
        if (tid < 3) g_b2c[tid] = b2[tid];
    }
}

// ---------------- per-point: trilerp + grad + MLP (f32x2) -------------------
__global__ void __launch_bounds__(256)
point_kernel(const float* __restrict__ ro, const float* __restrict__ rd,
             const float* __restrict__ vdir, const float* __restrict__ grid) {
    __shared__ float sW[CINC * HIDC];
    __shared__ float sB[HIDC];
    __shared__ float sW2[3 * HIDC];
    __shared__ float sB2[4];

    int idx = blockIdx.x * blockDim.x + threadIdx.x;   // NB*NS divisible by 256
    int ray = idx / NS;
    int s   = idx - ray * NS;

    // non-fused math to bit-match XLA's mul+add for the mask decision
    float lin = __fmul_rn((float)s, 1.0f / 499.0f);
    float z   = __fadd_rn(0.5f, __fmul_rn(3.0f, lin));
    float ox = ro[ray * 3 + 0], oy = ro[ray * 3 + 1], oz = ro[ray * 3 + 2];
    float dx = rd[ray * 3 + 0], dy = rd[ray * 3 + 1], dz = rd[ray * 3 + 2];
    float px = __fadd_rn(ox, __fmul_rn(dx, z));
    float py = __fadd_rn(oy, __fmul_rn(dy, z));
    float pz = __fadd_rn(oz, __fmul_rn(dz, z));

    bool outb = (px < -1.0f) | (px > 1.0f) | (py < -1.0f) | (py > 1.0f) |
                (pz < -1.0f) | (pz > 1.0f);
    if (outb) g_sdf[idx] = 100.0f;   // rgb untouched: weight is exactly 0

    int act = __syncthreads_count(!outb);
    if (act == 0) return;            // whole block outside: skip weights

    for (int i = threadIdx.x; i < CINC * HIDC; i += blockDim.x) sW[i] = g_cw[i];
    for (int i = threadIdx.x; i < HIDC; i += blockDim.x) sB[i] = g_cb[i];
    for (int i = threadIdx.x; i < 3 * HIDC; i += blockDim.x) sW2[i] = g_w2t[i];
    if (threadIdx.x < 3) sB2[threadIdx.x] = g_b2c[threadIdx.x];
    __syncthreads();
    if (outb) return;

    // ---- trilinear interp of 13 channels + analytic grad of channel 0 ----
    float ux = fminf(fmaxf((px + 1.0f) * 0.5f * 127.0f, 0.0f), 127.0f);
    float uy = fminf(fmaxf((py + 1.0f) * 0.5f * 127.0f, 0.0f), 127.0f);
    float uz = fminf(fmaxf((pz + 1.0f) * 0.5f * 127.0f, 0.0f), 127.0f);
    int ix = min((int)ux, RR - 2);
    int iy = min((int)uy, RR - 2);
    int iz = min((int)uz, RR - 2);
    float fx = ux - (float)ix, fy = uy - (float)iy, fz = uz - (float)iz;
    float wx[2] = {1.0f - fx, fx};
    float wy[2] = {1.0f - fy, fy};
    float wz[2] = {1.0f - fz, fz};

    const float* gp = grid + ((size_t)((ix * RR + iy) * RR + iz)) * GC;
    float vv[GC];
#pragma unroll
    for (int c = 0; c < GC; c++) vv[c] = 0.0f;
    float gxa = 0.0f, gya = 0.0f, gza = 0.0f;

#pragma unroll
    for (int cx = 0; cx < 2; cx++) {
#pragma unroll
        for (int cy = 0; cy < 2; cy++) {
#pragma unroll
            for (int cz = 0; cz < 2; cz++) {
                const float* cp = gp + cx * (RR * RR * GC) + cy * (RR * GC) + cz * GC;
                float wyz = wy[cy] * wz[cz];
                float wxz = wx[cx] * wz[cz];
                float wxy = wx[cx] * wy[cy];
                float w   = wx[cx] * wyz;
                float c0  = cp[0];
                vv[0] = fmaf(w, c0, vv[0]);
                gxa = fmaf(cx ? wyz : -wyz, c0, gxa);
                gya = fmaf(cy ? wxz : -wxz, c0, gya);
                gza = fmaf(cz ? wxy : -wxy, c0, gza);
#pragma unroll
                for (int c = 1; c < GC; c++) vv[c] = fmaf(w, cp[c], vv[c]);
            }
        }
    }

    // ---- assemble packed inputs {h,h} ----
    u64 hk2[CINC];
    hk2[0] = pack2(px, px); hk2[1] = pack2(py, py); hk2[2] = pack2(pz, pz);
    {
        float g0 = gxa * 63.5f, g1 = gya * 63.5f, g2 = gza * 63.5f;
        hk2[3] = pack2(g0, g0); hk2[4] = pack2(g1, g1); hk2[5] = pack2(g2, g2);
    }
    {
        float v0 = vdir[ray * 3 + 0], v1 = vdir[ray * 3 + 1], v2 = vdir[ray * 3 + 2];
        hk2[6] = pack2(v0, v0); hk2[7] = pack2(v1, v1); hk2[8] = pack2(v2, v2);
    }
#pragma unroll
    for (int l = 0; l < LATC; l++) hk2[9 + l] = pack2(vv[1 + l], vv[1 + l]);

    // ---- MLP with packed f32x2 FMAs ----
    const ulonglong2* sW8  = (const ulonglong2*)sW;
    const ulonglong2* sB8  = (const ulonglong2*)sB;
    const ulonglong2* sW28 = (const ulonglong2*)sW2;
    u64 r0p = pack2(0.f, 0.f), r1p = r0p, r2p = r0p;
    for (int jq = 0; jq < HIDC / 4; jq++) {
        ulonglong2 bq = sB8[jq];
        u64 a01 = bq.x, a23 = bq.y;
#pragma unroll
        for (int k = 0; k < CINC; k++) {
            ulonglong2 wv = sW8[k * (HIDC / 4) + jq];
            a01 = ffma2(wv.x, hk2[k], a01);
            a23 = ffma2(wv.y, hk2[k], a23);
        }
        // relu (unpack/repack)
        float t0, t1, t2, t3;
        unpack2(a01, t0, t1);
        unpack2(a23, t2, t3);
        a01 = pack2(fmaxf(t0, 0.f), fmaxf(t1, 0.f));
        a23 = pack2(fmaxf(t2, 0.f), fmaxf(t3, 0.f));
        ulonglong2 w0 = sW28[0 * (HIDC / 4) + jq];
        ulonglong2 w1 = sW28[1 * (HIDC / 4) + jq];
        ulonglong2 w2 = sW28[2 * (HIDC / 4) + jq];
        r0p = ffma2(a01, w0.x, r0p); r0p = ffma2(a23, w0.y, r0p);
        r1p = ffma2(a01, w1.x, r1p); r1p = ffma2(a23, w1.y, r1p);
        r2p = ffma2(a01, w2.x, r2p); r2p = ffma2(a23, w2.y, r2p);
    }
    float r0a, r0b, r1a, r1b, r2a, r2b;
    unpack2(r0p, r0a, r0b);
    unpack2(r1p, r1a, r1b);
    unpack2(r2p, r2a, r2b);
    float r0 = r0a + r0b, r1 = r1a + r1b, r2 = r2a + r2b;

    g_sdf[idx] = vv[0];
    g_rgbp[idx] = make_float4(
        1.0f / (1.0f + expf(-(r0 + sB2[0]))),
        1.0f / (1.0f + expf(-(r1 + sB2[1]))),
        1.0f / (1.0f + expf(-(r2 + sB2[2]))), 0.0f);
}

// ---------------- per-ray: transmittance scan + accumulation ----------------
__global__ void __launch_bounds__(256)
integrate_kernel(const float* __restrict__ rd, const float* __restrict__ beta_p,
                 float* __restrict__ out) {
    int gwarp = (blockIdx.x * blockDim.x + threadIdx.x) >> 5;
    int lane  = threadIdx.x & 31;
    if (gwarp >= NB) return;
    const unsigned FULL = 0xffffffffu;

    float beff = fabsf(beta_p[0]) + 1e-4f;
    float rb   = 1.0f / beff;
    float dx = rd[gwarp * 3 + 0], dy = rd[gwarp * 3 + 1], dz = rd[gwarp * 3 + 2];
    float dn = sqrtf(dx * dx + dy * dy + dz * dz);

    float carry = 0.0f, aR = 0.0f, aG = 0.0f, aB = 0.0f, aD = 0.0f;

    for (int chunk = 0; chunk < (NS + 31) / 32; chunk++) {
        int s = chunk * 32 + lane;
        bool in = s < NS;
        float sdf = in ? g_sdf[gwarp * NS + s] : 100.0f;

        float lin = __fmul_rn((float)s, 1.0f / 499.0f);
        float z   = __fadd_rn(0.5f, __fmul_rn(3.0f, lin));
        int sd = (s >= NS - 1) ? NS - 2 : s;
        float l0 = __fmul_rn((float)sd, 1.0f / 499.0f);
        float l1 = __fmul_rn((float)(sd + 1), 1.0f / 499.0f);
        float z0 = __fadd_rn(0.5f, __fmul_rn(3.0f, l0));
        float z1 = __fadd_rn(0.5f, __fmul_rn(3.0f, l1));
        float dist = z1 - z0;

        float asdf = fabsf(sdf);
        float sgn  = (sdf > 0.0f) ? 1.0f : ((sdf < 0.0f) ? -1.0f : 0.0f);
        float density = rb * (0.5f + 0.5f * sgn * expm1f(-asdf / beff));
        float fe = in ? dist * density : 0.0f;

        // inclusive warp scan of fe
        float sc = fe;
#pragma unroll
        for (int o = 1; o < 32; o <<= 1) {
            float t = __shfl_up_sync(FULL, sc, o);
            if (lane >= o) sc += t;
        }
        float T     = expf(-(carry + (sc - fe)));   // exclusive prefix
        float alpha = 1.0f - expf(-fe);
        float w     = in ? alpha * T : 0.0f;

        if (in && w != 0.0f) {
            float4 c = g_rgbp[gwarp * NS + s];
            aR = fmaf(w, c.x, aR);
            aG = fmaf(w, c.y, aG);
            aB = fmaf(w, c.z, aB);
        }
        if (in) aD = fmaf(w, z * dn, aD);
        carry += __shfl_sync(FULL, sc, 31);
    }

#pragma unroll
    for (int o = 16; o > 0; o >>= 1) {
        aR += __shfl_down_sync(FULL, aR, o);
        aG += __shfl_down_sync(FULL, aG, o);
        aB += __shfl_down_sync(FULL, aB, o);
        aD += __shfl_down_sync(FULL, aD, o);
    }
    if (lane == 0) {
        out[gwarp * 3 + 0] = aR;
        out[gwarp * 3 + 1] = aG;
        out[gwarp * 3 + 2] = aB;
        out[3 * NB + gwarp] = aD;
    }
}

// ---------------- launch -----------------------------------------------------
extern "C" void kernel_launch(void* const* d_in, const int* in_sizes, int n_in,
                              void* d_out, int out_size) {
    const float* ro   = (const float*)d_in[0];
    const float* rd   = (const float*)d_in[1];
    const float* vd   = (const float*)d_in[2];
    const float* grid = (const float*)d_in[3];
    const float* Wf   = (const float*)d_in[4];
    const float* bf   = (const float*)d_in[5];
    const float* W1   = (const float*)d_in[6];
    const float* b1   = (const float*)d_in[7];
    const float* W2   = (const float*)d_in[8];
    const float* b2   = (const float*)d_in[9];
    const float* beta = (const float*)d_in[10];
    float* out = (float*)d_out;

    fold_kernel<<<LATC + 1, 512>>>(Wf, bf, W1, b1, W2, b2);
    point_kernel<<<(NB * NS) / 256, 256>>>(ro, rd, vd, grid);
    integrate_kernel<<<(NB * 32 + 255) / 256, 256>>>(rd, beta, out);
}